// round 6
// baseline (speedup 1.0000x reference)
#include <cuda_runtime.h>
#include <cstdint>

// OnlineEmbedding: out[r, :] = table[ids[r], :]
//   ids:   [819200] int32, values in [0, 1e6)
//   table: [1e6, 64] float32 (row = 256 B = 16 float4)
//   out:   [819200, 64] float32
//
// R5 -> R6: revert to the R2 memory ops (plain __ldg float4 gathers, __stcs
// stores — fastest measured), but make the kernel PERSISTENT:
// exactly one wave (148 SMs x 8 CTAs x 256 thr), grid-stride over all row
// groups. Eliminates ~10 wave transitions (~2360 cyc each per SM) that a
// 12800-CTA launch pays, and pipelines store-tail with next-iter loads.

static constexpr int ROWS         = 4096 * 200;  // 819200
static constexpr int ROWS_PER_GRP = 4;
static constexpr int THR_PER_ROW  = 16;
static constexpr int F4_PER_ROW   = 16;
static constexpr int NUM_GROUPS   = ROWS / ROWS_PER_GRP;   // 204800

static constexpr int BLOCK        = 256;
static constexpr int GRID         = 148 * 8;               // one full wave

__global__ __launch_bounds__(BLOCK, 8)
void embed_gather_kernel(const int* __restrict__ ids,
                         const float4* __restrict__ table,
                         float4* __restrict__ out)
{
    const int lane      = threadIdx.x & 15;                 // float4 idx in row
    const int grp_local = (blockIdx.x * BLOCK + threadIdx.x) >> 4;
    const int grp_step  = (GRID * BLOCK) >> 4;              // groups per wave

    for (int grp = grp_local; grp < NUM_GROUPS; grp += grp_step) {
        const int row0 = grp * ROWS_PER_GRP;

        int4 id4 = __ldcs((const int4*)(ids + row0));

        float4 v0 = __ldg(table + (size_t)id4.x * F4_PER_ROW + lane);
        float4 v1 = __ldg(table + (size_t)id4.y * F4_PER_ROW + lane);
        float4 v2 = __ldg(table + (size_t)id4.z * F4_PER_ROW + lane);
        float4 v3 = __ldg(table + (size_t)id4.w * F4_PER_ROW + lane);

        float4* o = out + (size_t)row0 * F4_PER_ROW + lane;
        __stcs(o + 0 * F4_PER_ROW, v0);
        __stcs(o + 1 * F4_PER_ROW, v1);
        __stcs(o + 2 * F4_PER_ROW, v2);
        __stcs(o + 3 * F4_PER_ROW, v3);
    }
}

extern "C" void kernel_launch(void* const* d_in, const int* in_sizes, int n_in,
                              void* d_out, int out_size)
{
    const int*    ids   = (const int*)d_in[0];
    const float4* table = (const float4*)d_in[1];
    float4*       out   = (float4*)d_out;

    embed_gather_kernel<<<GRID, BLOCK>>>(ids, table, out);
}

// round 7
// speedup vs baseline: 1.1256x; 1.1256x over previous
#include <cuda_runtime.h>
#include <cstdint>

// OnlineEmbedding: out[r, :] = table[ids[r], :]
//   ids:   [819200] int32, values in [0, 1e6)
//   table: [1e6, 64] float32 (row = 256 B = 16 float4)
//   out:   [819200, 64] float32
//
// R6 -> R7: revert to the R2 shape (best measured: 57.4us kernel), single
// isolated change: table gathers use __ldcg (L2-only, bypass L1).
// Random 256B rows have zero L1 reuse; bypassing L1 removes the tag-stage
// and L1tex wavefront occupancy from the critical gather path.
//  - 4 rows per 16-thread group, one int4 id load, 4 independent gathers.
//  - __stcs output (evict-first write stream).

static constexpr int ROWS         = 4096 * 200;  // 819200
static constexpr int ROWS_PER_GRP = 4;
static constexpr int THR_PER_ROW  = 16;
static constexpr int F4_PER_ROW   = 16;

__global__ __launch_bounds__(256)
void embed_gather_kernel(const int* __restrict__ ids,
                         const float4* __restrict__ table,
                         float4* __restrict__ out)
{
    int gtid = blockIdx.x * blockDim.x + threadIdx.x;
    int grp  = gtid >> 4;            // group of 16 threads
    int lane = gtid & 15;            // float4 index within row
    int row0 = grp * ROWS_PER_GRP;
    if (row0 >= ROWS) return;

    int4 id4 = __ldcs((const int4*)(ids + row0));

    // 4 independent L2-only gathers.
    float4 v0 = __ldcg(table + (size_t)id4.x * F4_PER_ROW + lane);
    float4 v1 = __ldcg(table + (size_t)id4.y * F4_PER_ROW + lane);
    float4 v2 = __ldcg(table + (size_t)id4.z * F4_PER_ROW + lane);
    float4 v3 = __ldcg(table + (size_t)id4.w * F4_PER_ROW + lane);

    float4* o = out + (size_t)row0 * F4_PER_ROW + lane;
    __stcs(o + 0 * F4_PER_ROW, v0);
    __stcs(o + 1 * F4_PER_ROW, v1);
    __stcs(o + 2 * F4_PER_ROW, v2);
    __stcs(o + 3 * F4_PER_ROW, v3);
}

extern "C" void kernel_launch(void* const* d_in, const int* in_sizes, int n_in,
                              void* d_out, int out_size)
{
    const int*    ids   = (const int*)d_in[0];
    const float4* table = (const float4*)d_in[1];
    float4*       out   = (float4*)d_out;

    const int groups        = ROWS / ROWS_PER_GRP;          // 204800
    const int total_threads = groups * THR_PER_ROW;         // 3,276,800
    const int block = 256;
    const int grid  = (total_threads + block - 1) / block;  // 12800

    embed_gather_kernel<<<grid, block>>>(ids, table, out);
}